// round 9
// baseline (speedup 1.0000x reference)
#include <cuda_runtime.h>
#include <cuda_bf16.h>

#define N_NODES 100000
#define N_EDGES 3200000
#define N_GRAPHS 256
// DIMS: 38 -> 64 -> 32 -> 16

// ---------------- scratch (static device globals; no allocs) ----------------
__device__ float g_x40 [N_NODES * 40];
__device__ float g_agg0[N_NODES * 40];
__device__ float g_agg1[N_NODES * 32];
__device__ float g_agg2[N_NODES * 16];
__device__ float g_h1[N_NODES * 64];
__device__ float g_h2[N_NODES * 32];
__device__ float g_y1[N_NODES * 32];
__device__ float g_y2[N_NODES * 16];
__device__ int   g_src[N_EDGES];
__device__ int   g_dst[N_EDGES];
__device__ float g_pool[N_GRAPHS * 16];
__device__ float g_cnt[N_GRAPHS];
__device__ int   g_ei_is64;
__device__ int   g_b_is64;

__device__ __forceinline__ void red_add_v4(float* addr, float4 v) {
    asm volatile("red.global.add.v4.f32 [%0], {%1,%2,%3,%4};"
                 :: "l"(addr), "f"(v.x), "f"(v.y), "f"(v.z), "f"(v.w)
                 : "memory");
}

// ---------------- dtype detection (int32 vs int64 buffers) ------------------
__global__ void k_detect(const int* __restrict__ ei_raw,
                         const int* __restrict__ b_raw) {
    int nz = 0;
    #pragma unroll
    for (int i = 0; i < 64; i++) nz |= ei_raw[2 * i + 1];
    g_ei_is64 = (nz == 0) ? 1 : 0;
    g_b_is64 = (b_raw[N_NODES - 1] == 0) ? 1 : 0;
}

// ---------------- fused prep: convert indices + zero + pack x ---------------
__global__ void k_prep(const float* __restrict__ x,
                       const int* __restrict__ ei_raw) {
    long long i = (long long)blockIdx.x * blockDim.x + threadIdx.x;
    long long stride = (long long)gridDim.x * blockDim.x;
    int is64 = g_ei_is64;
    for (long long e = i; e < N_EDGES; e += stride) {
        if (is64) {
            g_src[e] = ei_raw[2 * e];
            g_dst[e] = ei_raw[2 * ((long long)N_EDGES + e)];
        } else {
            g_src[e] = ei_raw[e];
            g_dst[e] = ei_raw[N_EDGES + e];
        }
    }
    for (long long k = i; k < (long long)N_NODES * 40; k += stride) {
        g_agg0[k] = 0.f;
        int j = (int)(k % 40);
        g_x40[k] = (j < 38) ? x[(k / 40) * 38 + j] : 0.f;
    }
    for (long long k = i; k < (long long)N_NODES * 32; k += stride) g_agg1[k] = 0.f;
    for (long long k = i; k < (long long)N_NODES * 16; k += stride) g_agg2[k] = 0.f;
    for (long long k = i; k < N_GRAPHS * 16; k += stride) g_pool[k] = 0.f;
    for (long long k = i; k < N_GRAPHS; k += stride) g_cnt[k] = 0.f;
}

// ---------------- scatters (unchanged; at REDG-lane floor) ------------------
__global__ void k_scatter0() {
    long long idx = (long long)blockIdx.x * blockDim.x + threadIdx.x;
    if (idx >= (long long)N_EDGES * 10) return;
    int e = (int)(idx / 10);
    int c = (int)(idx - (long long)e * 10);
    int s = g_src[e];
    int d = g_dst[e];
    float4 v = *(const float4*)&g_x40[s * 40 + c * 4];
    red_add_v4(&g_agg0[d * 40 + c * 4], v);
}

__global__ void k_scatter1() {
    long long idx = (long long)blockIdx.x * blockDim.x + threadIdx.x;
    if (idx >= (long long)N_EDGES * 8) return;
    int e = (int)(idx >> 3);
    int c = (int)(idx & 7);
    int s = g_src[e];
    int d = g_dst[e];
    float4 v = *(const float4*)&g_y1[s * 32 + c * 4];
    red_add_v4(&g_agg1[d * 32 + c * 4], v);
}

__global__ void k_scatter2() {
    long long idx = (long long)blockIdx.x * blockDim.x + threadIdx.x;
    if (idx >= (long long)N_EDGES * 4) return;
    int e = (int)(idx >> 2);
    int c = (int)(idx & 3);
    int s = g_src[e];
    int d = g_dst[e];
    float4 v = *(const float4*)&g_y2[s * 16 + c * 4];
    red_add_v4(&g_agg2[d * 16 + c * 4], v);
}

// ---------------- node kernel 0: activation-stationary ----------------------
// lane = node (warp covers 32 nodes; block covers 256 nodes per iteration).
// Activations (agg0, x) in registers; weight rows broadcast from shared.
// y1 computed as a fused outer product into 32 register accumulators.
__global__ void k_node0(const float* __restrict__ Wr0,  // [64,38]
                        const float* __restrict__ b0,   // [64]
                        const float* __restrict__ Wt0,  // [64,38]
                        const float* __restrict__ Wr1)  // [32,64]
{
    __shared__ float sWr[64 * 40];   // Wr0 rows padded to 40
    __shared__ float sWt[64 * 40];   // Wt0 rows padded to 40
    __shared__ float sW1T[64 * 32];  // Wr1 transposed: sW1T[o*32+oo] = Wr1[oo][o]
    __shared__ float sb0[64];
    int t = threadIdx.x;
    int lane = t & 31, wid = t >> 5;
    for (int i = t; i < 64 * 40; i += 256) {
        int o = i / 40, j = i % 40;
        float vr = (j < 38) ? Wr0[o * 38 + j] : 0.f;
        float vt = (j < 38) ? Wt0[o * 38 + j] : 0.f;
        sWr[i] = vr; sWt[i] = vt;
    }
    for (int i = t; i < 64 * 32; i += 256) {
        int o = i >> 5, oo = i & 31;
        sW1T[i] = Wr1[oo * 64 + o];
    }
    if (t < 64) sb0[t] = b0[t];
    __syncthreads();

    for (int nbase = blockIdx.x * 256; nbase < N_NODES; nbase += gridDim.x * 256) {
        int node = nbase + wid * 32 + lane;
        bool valid = node < N_NODES;
        int nc = valid ? node : (N_NODES - 1);     // clamp for safe loads
        float4 a4[10], x4[10];
        #pragma unroll
        for (int c = 0; c < 10; c++) {
            a4[c] = *(const float4*)&g_agg0[nc * 40 + c * 4];
            x4[c] = *(const float4*)&g_x40 [nc * 40 + c * 4];
        }
        float acc[32];
        #pragma unroll
        for (int i = 0; i < 32; i++) acc[i] = 0.f;

        #pragma unroll
        for (int og = 0; og < 16; og++) {
            float hk[4];
            #pragma unroll
            for (int k = 0; k < 4; k++) {
                int o = og * 4 + k;
                float h = sb0[o];
                const float* wr = &sWr[o * 40];
                const float* wt = &sWt[o * 40];
                #pragma unroll
                for (int c = 0; c < 10; c++) {
                    float4 w = *(const float4*)&wr[c * 4];  // broadcast
                    float4 u = *(const float4*)&wt[c * 4];  // broadcast
                    h += w.x*a4[c].x + w.y*a4[c].y + w.z*a4[c].z + w.w*a4[c].w
                       + u.x*x4[c].x + u.y*x4[c].y + u.z*x4[c].z + u.w*x4[c].w;
                }
                h = tanhf(h);
                hk[k] = h;
                const float* w1 = &sW1T[o * 32];
                #pragma unroll
                for (int c2 = 0; c2 < 8; c2++) {
                    float4 wv = *(const float4*)&w1[c2 * 4]; // broadcast
                    acc[4*c2+0] += wv.x * h;
                    acc[4*c2+1] += wv.y * h;
                    acc[4*c2+2] += wv.z * h;
                    acc[4*c2+3] += wv.w * h;
                }
            }
            if (valid)
                *(float4*)&g_h1[node * 64 + og * 4] =
                    make_float4(hk[0], hk[1], hk[2], hk[3]);
        }
        if (valid) {
            #pragma unroll
            for (int c2 = 0; c2 < 8; c2++)
                *(float4*)&g_y1[node * 32 + c2 * 4] =
                    make_float4(acc[4*c2+0], acc[4*c2+1], acc[4*c2+2], acc[4*c2+3]);
        }
    }
}

// ---------------- node kernel 1: 32 nodes/iter, ILP=4 (unchanged) -----------
__global__ void k_node1(const float* __restrict__ b1,   // [32]
                        const float* __restrict__ Wt1,  // [32,64]
                        const float* __restrict__ Wr2)  // [16,32]
{
    int t = threadIdx.x;
    int o = t & 31, sl = t >> 5;
    float wt1[64];
    #pragma unroll
    for (int j = 0; j < 64; j++) wt1[j] = Wt1[o * 64 + j];
    float bias = b1[o];
    int oo = o & 15, jb = (o < 16) ? 0 : 16;

    __shared__ float sW2[16 * 33];           // Wr2 [16x32] row stride 33
    __shared__ float sh1[32][64];
    __shared__ float sh2[32][32];
    for (int i = t; i < 16 * 32; i += 256) sW2[(i >> 5) * 33 + (i & 31)] = Wr2[i];
    __syncthreads();

    for (int nbase = blockIdx.x * 32; nbase < N_NODES; nbase += gridDim.x * 32) {
        for (int i = t; i < 512; i += 256) {
            int n2 = i >> 4, r = i & 15;
            int nn = nbase + n2;
            if (nn < N_NODES)
                *(float4*)&sh1[n2][r * 4] = *(const float4*)&g_h1[nn * 64 + r * 4];
        }
        __syncthreads();
        float hq[4];
        #pragma unroll
        for (int q = 0; q < 4; q++) {
            int nl = sl + 8 * q, node = nbase + nl;
            float h = bias;
            if (node < N_NODES) h += g_agg1[node * 32 + o];
            #pragma unroll
            for (int c = 0; c < 16; c++) {
                float4 hv = *(const float4*)&sh1[nl][c * 4];
                h += wt1[4*c+0]*hv.x + wt1[4*c+1]*hv.y + wt1[4*c+2]*hv.z + wt1[4*c+3]*hv.w;
            }
            hq[q] = tanhf(h);
        }
        #pragma unroll
        for (int q = 0; q < 4; q++) {
            int nl = sl + 8 * q, node = nbase + nl;
            if (node < N_NODES) g_h2[node * 32 + o] = hq[q];
            sh2[nl][o] = hq[q];
        }
        __syncwarp();
        #pragma unroll
        for (int q = 0; q < 4; q++) {
            int nl = sl + 8 * q, node = nbase + nl;
            float p = 0.f;
            #pragma unroll
            for (int c = 0; c < 4; c++) {
                float4 hv = *(const float4*)&sh2[nl][jb + c * 4];
                const float* wrow = &sW2[oo * 33 + jb + c * 4];
                p += wrow[0]*hv.x + wrow[1]*hv.y + wrow[2]*hv.z + wrow[3]*hv.w;
            }
            float other = __shfl_down_sync(0xffffffffu, p, 16);
            if (node < N_NODES && o < 16) g_y2[node * 16 + o] = p + other;
        }
        __syncthreads();
    }
}

// ---------------- node kernel 2 + pooling: 64 nodes/iter, ILP=4 (unchanged) -
__global__ void k_node2_pool(const int* __restrict__ batch_raw,
                             const float* __restrict__ b2,   // [16]
                             const float* __restrict__ Wt2)  // [16,32]
{
    int t = threadIdx.x;
    int o = t & 15, sl = t >> 4;
    float wt2[32];
    #pragma unroll
    for (int j = 0; j < 32; j++) wt2[j] = Wt2[o * 32 + j];
    float bias = b2[o];
    int b_is64 = g_b_is64;

    __shared__ float sh2[64][32];

    for (int nbase = blockIdx.x * 64; nbase < N_NODES; nbase += gridDim.x * 64) {
        for (int i = t; i < 512; i += 256) {
            int n2 = i >> 3, r = i & 7;
            int nn = nbase + n2;
            if (nn < N_NODES)
                *(float4*)&sh2[n2][r * 4] = *(const float4*)&g_h2[nn * 32 + r * 4];
        }
        __syncthreads();
        #pragma unroll
        for (int q = 0; q < 4; q++) {
            int nl = sl + 16 * q, node = nbase + nl;
            if (node < N_NODES) {
                float acc = bias + g_agg2[node * 16 + o];
                #pragma unroll
                for (int c = 0; c < 8; c++) {
                    float4 hv = *(const float4*)&sh2[nl][c * 4];
                    acc += wt2[4*c+0]*hv.x + wt2[4*c+1]*hv.y + wt2[4*c+2]*hv.z + wt2[4*c+3]*hv.w;
                }
                int g = b_is64 ? batch_raw[2 * node] : batch_raw[node];
                atomicAdd(&g_pool[g * 16 + o], acc);
                if (o == 0) atomicAdd(&g_cnt[g], 1.0f);
            }
        }
        __syncthreads();
    }
}

// ---------------- final: out = tanh(pool / max(cnt,1)) ----------------------
__global__ void k_final(float* __restrict__ out) {
    int t = blockIdx.x * blockDim.x + threadIdx.x;
    if (t < N_GRAPHS * 16) {
        int g = t >> 4;
        out[t] = tanhf(g_pool[t] / fmaxf(g_cnt[g], 1.0f));
    }
}

extern "C" void kernel_launch(void* const* d_in, const int* in_sizes, int n_in,
                              void* d_out, int out_size) {
    const float* x         = (const float*)d_in[0];
    const int*   ei_raw    = (const int*)d_in[1];
    const int*   batch_raw = (const int*)d_in[2];
    const float* Wr0 = (const float*)d_in[3];
    const float* b0  = (const float*)d_in[4];
    const float* Wt0 = (const float*)d_in[5];
    const float* Wr1 = (const float*)d_in[6];
    const float* b1  = (const float*)d_in[7];
    const float* Wt1 = (const float*)d_in[8];
    const float* Wr2 = (const float*)d_in[9];
    const float* b2  = (const float*)d_in[10];
    const float* Wt2 = (const float*)d_in[11];
    float* out = (float*)d_out;

    k_detect<<<1, 1>>>(ei_raw, batch_raw);
    k_prep<<<2048, 256>>>(x, ei_raw);
    k_scatter0<<<(int)(((long long)N_EDGES * 10 + 255) / 256), 256>>>();
    k_node0<<<296, 256>>>(Wr0, b0, Wt0, Wr1);
    k_scatter1<<<(int)(((long long)N_EDGES * 8 + 255) / 256), 256>>>();
    k_node1<<<296, 256>>>(b1, Wt1, Wr2);
    k_scatter2<<<(int)(((long long)N_EDGES * 4 + 255) / 256), 256>>>();
    k_node2_pool<<<296, 256>>>(batch_raw, b2, Wt2);
    k_final<<<16, 256>>>(out);
}

// round 10
// speedup vs baseline: 1.0173x; 1.0173x over previous
#include <cuda_runtime.h>
#include <cuda_bf16.h>

#define N_NODES 100000
#define N_EDGES 3200000
#define N_GRAPHS 256
// DIMS: 38 -> 64 -> 32 -> 16

// ---------------- scratch (static device globals; no allocs) ----------------
__device__ float g_x40 [N_NODES * 40];
__device__ float g_agg0[N_NODES * 40];
__device__ float g_agg1[N_NODES * 32];
__device__ float g_agg2[N_NODES * 16];
__device__ float g_h1[N_NODES * 64];
__device__ float g_h2[N_NODES * 32];
__device__ float g_y1[N_NODES * 32];
__device__ float g_y2[N_NODES * 16];
__device__ int   g_src[N_EDGES];
__device__ int   g_dst[N_EDGES];
__device__ int   g_ssrc[N_EDGES];       // src sorted by dst (CSR)
__device__ int   g_rowptr[N_NODES + 1];
__device__ int   g_cursor[N_NODES];     // degree counter, then placement cursor
__device__ int   g_blocksum[512];
__device__ float g_pool[N_GRAPHS * 16];
__device__ float g_cnt[N_GRAPHS];
__device__ int   g_ei_is64;
__device__ int   g_b_is64;

// ---------------- dtype detection (int32 vs int64 buffers) ------------------
__global__ void k_detect(const int* __restrict__ ei_raw,
                         const int* __restrict__ b_raw) {
    int nz = 0;
    #pragma unroll
    for (int i = 0; i < 64; i++) nz |= ei_raw[2 * i + 1];
    g_ei_is64 = (nz == 0) ? 1 : 0;
    g_b_is64 = (b_raw[N_NODES - 1] == 0) ? 1 : 0;
}

// ---------------- prep: convert indices, pack x, zero small bufs ------------
__global__ void k_prep(const float* __restrict__ x,
                       const int* __restrict__ ei_raw) {
    long long i = (long long)blockIdx.x * blockDim.x + threadIdx.x;
    long long stride = (long long)gridDim.x * blockDim.x;
    int is64 = g_ei_is64;
    for (long long e = i; e < N_EDGES; e += stride) {
        if (is64) {
            g_src[e] = ei_raw[2 * e];
            g_dst[e] = ei_raw[2 * ((long long)N_EDGES + e)];
        } else {
            g_src[e] = ei_raw[e];
            g_dst[e] = ei_raw[N_EDGES + e];
        }
    }
    for (long long k = i; k < (long long)N_NODES * 40; k += stride) {
        int j = (int)(k % 40);
        g_x40[k] = (j < 38) ? x[(k / 40) * 38 + j] : 0.f;
    }
    for (long long k = i; k < N_NODES; k += stride) g_cursor[k] = 0;
    for (long long k = i; k < N_GRAPHS * 16; k += stride) g_pool[k] = 0.f;
    for (long long k = i; k < N_GRAPHS; k += stride) g_cnt[k] = 0.f;
}

// ---------------- CSR build: histogram -> scan -> place ---------------------
__global__ void k_hist() {
    int i = blockIdx.x * blockDim.x + threadIdx.x;
    int stride = gridDim.x * blockDim.x;
    for (int e = i; e < N_EDGES; e += stride)
        atomicAdd(&g_cursor[g_dst[e]], 1);
}

__global__ void k_scan1() {   // per-block exclusive scan of degrees
    __shared__ int sh[256];
    int i = blockIdx.x * 256 + threadIdx.x;
    int v = (i < N_NODES) ? g_cursor[i] : 0;
    sh[threadIdx.x] = v;
    __syncthreads();
    for (int off = 1; off < 256; off <<= 1) {
        int t = (threadIdx.x >= off) ? sh[threadIdx.x - off] : 0;
        __syncthreads();
        sh[threadIdx.x] += t;
        __syncthreads();
    }
    if (i < N_NODES) g_rowptr[i] = sh[threadIdx.x] - v;   // exclusive
    if (threadIdx.x == 255) g_blocksum[blockIdx.x] = sh[255];
}

__global__ void k_scan2() {   // scan of 391 block sums (1 block, 512 threads)
    __shared__ int sh[512];
    int v = (threadIdx.x < 391) ? g_blocksum[threadIdx.x] : 0;
    sh[threadIdx.x] = v;
    __syncthreads();
    for (int off = 1; off < 512; off <<= 1) {
        int t = (threadIdx.x >= off) ? sh[threadIdx.x - off] : 0;
        __syncthreads();
        sh[threadIdx.x] += t;
        __syncthreads();
    }
    if (threadIdx.x < 391) g_blocksum[threadIdx.x] = sh[threadIdx.x] - v;
}

__global__ void k_scan3() {   // add block offsets; init cursors
    int i = blockIdx.x * 256 + threadIdx.x;
    if (i < N_NODES) {
        int r = g_rowptr[i] + g_blocksum[blockIdx.x];
        g_rowptr[i] = r;
        g_cursor[i] = r;
    }
    if (i == 0) g_rowptr[N_NODES] = N_EDGES;
}

__global__ void k_place() {
    int i = blockIdx.x * blockDim.x + threadIdx.x;
    int stride = gridDim.x * blockDim.x;
    for (int e = i; e < N_EDGES; e += stride) {
        int d = g_dst[e];
        int p = atomicAdd(&g_cursor[d], 1);
        g_ssrc[p] = g_src[e];
    }
}

// ---------------- CSR gather-sum aggregations -------------------------------
// thread = (node, float4-chunk). Register accumulate, one store. No pre-zero.
__global__ void k_agg0() {
    int idx = blockIdx.x * blockDim.x + threadIdx.x;
    if (idx >= N_NODES * 10) return;
    int n = idx / 10, c = idx - n * 10;
    int beg = g_rowptr[n], end = g_rowptr[n + 1];
    float4 a0 = make_float4(0.f, 0.f, 0.f, 0.f);
    float4 a1 = make_float4(0.f, 0.f, 0.f, 0.f);
    int k = beg;
    for (; k + 2 <= end; k += 2) {
        int s0 = g_ssrc[k], s1 = g_ssrc[k + 1];
        float4 v0 = *(const float4*)&g_x40[s0 * 40 + c * 4];
        float4 v1 = *(const float4*)&g_x40[s1 * 40 + c * 4];
        a0.x += v0.x; a0.y += v0.y; a0.z += v0.z; a0.w += v0.w;
        a1.x += v1.x; a1.y += v1.y; a1.z += v1.z; a1.w += v1.w;
    }
    if (k < end) {
        int s = g_ssrc[k];
        float4 v = *(const float4*)&g_x40[s * 40 + c * 4];
        a0.x += v.x; a0.y += v.y; a0.z += v.z; a0.w += v.w;
    }
    *(float4*)&g_agg0[n * 40 + c * 4] =
        make_float4(a0.x + a1.x, a0.y + a1.y, a0.z + a1.z, a0.w + a1.w);
}

__global__ void k_agg1() {
    int idx = blockIdx.x * blockDim.x + threadIdx.x;
    if (idx >= N_NODES * 8) return;
    int n = idx >> 3, c = idx & 7;
    int beg = g_rowptr[n], end = g_rowptr[n + 1];
    float4 a0 = make_float4(0.f, 0.f, 0.f, 0.f);
    float4 a1 = make_float4(0.f, 0.f, 0.f, 0.f);
    int k = beg;
    for (; k + 2 <= end; k += 2) {
        int s0 = g_ssrc[k], s1 = g_ssrc[k + 1];
        float4 v0 = *(const float4*)&g_y1[s0 * 32 + c * 4];
        float4 v1 = *(const float4*)&g_y1[s1 * 32 + c * 4];
        a0.x += v0.x; a0.y += v0.y; a0.z += v0.z; a0.w += v0.w;
        a1.x += v1.x; a1.y += v1.y; a1.z += v1.z; a1.w += v1.w;
    }
    if (k < end) {
        int s = g_ssrc[k];
        float4 v = *(const float4*)&g_y1[s * 32 + c * 4];
        a0.x += v.x; a0.y += v.y; a0.z += v.z; a0.w += v.w;
    }
    *(float4*)&g_agg1[n * 32 + c * 4] =
        make_float4(a0.x + a1.x, a0.y + a1.y, a0.z + a1.z, a0.w + a1.w);
}

__global__ void k_agg2() {
    int idx = blockIdx.x * blockDim.x + threadIdx.x;
    if (idx >= N_NODES * 4) return;
    int n = idx >> 2, c = idx & 3;
    int beg = g_rowptr[n], end = g_rowptr[n + 1];
    float4 a0 = make_float4(0.f, 0.f, 0.f, 0.f);
    float4 a1 = make_float4(0.f, 0.f, 0.f, 0.f);
    int k = beg;
    for (; k + 2 <= end; k += 2) {
        int s0 = g_ssrc[k], s1 = g_ssrc[k + 1];
        float4 v0 = *(const float4*)&g_y2[s0 * 16 + c * 4];
        float4 v1 = *(const float4*)&g_y2[s1 * 16 + c * 4];
        a0.x += v0.x; a0.y += v0.y; a0.z += v0.z; a0.w += v0.w;
        a1.x += v1.x; a1.y += v1.y; a1.z += v1.z; a1.w += v1.w;
    }
    if (k < end) {
        int s = g_ssrc[k];
        float4 v = *(const float4*)&g_y2[s * 16 + c * 4];
        a0.x += v.x; a0.y += v.y; a0.z += v.z; a0.w += v.w;
    }
    *(float4*)&g_agg2[n * 16 + c * 4] =
        make_float4(a0.x + a1.x, a0.y + a1.y, a0.z + a1.z, a0.w + a1.w);
}

// ---------------- node0 phase A: h1 only (activation-stationary) ------------
// lane = node; activations in 80 regs; weight rows are warp-uniform broadcasts.
__global__ void __launch_bounds__(256, 2)
k_node0A(const float* __restrict__ Wr0,  // [64,38]
         const float* __restrict__ b0,   // [64]
         const float* __restrict__ Wt0)  // [64,38]
{
    __shared__ float sWr[64 * 40], sWt[64 * 40], sb0[64];
    int t = threadIdx.x;
    int lane = t & 31, wid = t >> 5;
    for (int i = t; i < 64 * 40; i += 256) {
        int o = i / 40, j = i % 40;
        sWr[i] = (j < 38) ? Wr0[o * 38 + j] : 0.f;
        sWt[i] = (j < 38) ? Wt0[o * 38 + j] : 0.f;
    }
    if (t < 64) sb0[t] = b0[t];
    __syncthreads();

    for (int nbase = blockIdx.x * 256; nbase < N_NODES; nbase += gridDim.x * 256) {
        int node = nbase + wid * 32 + lane;
        bool valid = node < N_NODES;
        int nc = valid ? node : (N_NODES - 1);
        float4 a4[10], x4[10];
        #pragma unroll
        for (int c = 0; c < 10; c++) {
            a4[c] = *(const float4*)&g_agg0[nc * 40 + c * 4];
            x4[c] = *(const float4*)&g_x40 [nc * 40 + c * 4];
        }
        #pragma unroll
        for (int og = 0; og < 16; og++) {
            float hk[4];
            #pragma unroll
            for (int k = 0; k < 4; k++) {
                int o = og * 4 + k;
                float h = sb0[o];
                const float* wr = &sWr[o * 40];
                const float* wt = &sWt[o * 40];
                #pragma unroll
                for (int c = 0; c < 10; c++) {
                    float4 w = *(const float4*)&wr[c * 4];
                    float4 u = *(const float4*)&wt[c * 4];
                    h += w.x*a4[c].x + w.y*a4[c].y + w.z*a4[c].z + w.w*a4[c].w
                       + u.x*x4[c].x + u.y*x4[c].y + u.z*x4[c].z + u.w*x4[c].w;
                }
                hk[k] = tanhf(h);
            }
            if (valid)
                *(float4*)&g_h1[node * 64 + og * 4] =
                    make_float4(hk[0], hk[1], hk[2], hk[3]);
        }
    }
}

// ---------------- node0 phase B: y1 = h1 @ Wr1^T (outer product) ------------
__global__ void __launch_bounds__(256, 2)
k_y1(const float* __restrict__ Wr1)       // [32,64]
{
    __shared__ float sW1T[64 * 32];       // sW1T[o*32+oo] = Wr1[oo][o]
    int t = threadIdx.x;
    int lane = t & 31, wid = t >> 5;
    for (int i = t; i < 64 * 32; i += 256) {
        int o = i >> 5, oo = i & 31;
        sW1T[i] = Wr1[oo * 64 + o];
    }
    __syncthreads();

    for (int nbase = blockIdx.x * 256; nbase < N_NODES; nbase += gridDim.x * 256) {
        int node = nbase + wid * 32 + lane;
        bool valid = node < N_NODES;
        int nc = valid ? node : (N_NODES - 1);
        float4 h4[16];
        #pragma unroll
        for (int c = 0; c < 16; c++)
            h4[c] = *(const float4*)&g_h1[nc * 64 + c * 4];
        float acc[32];
        #pragma unroll
        for (int i = 0; i < 32; i++) acc[i] = 0.f;
        #pragma unroll
        for (int o = 0; o < 64; o++) {
            float4 q = h4[o >> 2];
            int r = o & 3;
            float h = (r == 0) ? q.x : (r == 1) ? q.y : (r == 2) ? q.z : q.w;
            const float* w1 = &sW1T[o * 32];
            #pragma unroll
            for (int c2 = 0; c2 < 8; c2++) {
                float4 wv = *(const float4*)&w1[c2 * 4];  // broadcast
                acc[4*c2+0] += wv.x * h;
                acc[4*c2+1] += wv.y * h;
                acc[4*c2+2] += wv.z * h;
                acc[4*c2+3] += wv.w * h;
            }
        }
        if (valid) {
            #pragma unroll
            for (int c2 = 0; c2 < 8; c2++)
                *(float4*)&g_y1[node * 32 + c2 * 4] =
                    make_float4(acc[4*c2+0], acc[4*c2+1], acc[4*c2+2], acc[4*c2+3]);
        }
    }
}

// ---------------- node kernel 1: 32 nodes/iter, ILP=4 (unchanged) -----------
__global__ void k_node1(const float* __restrict__ b1,   // [32]
                        const float* __restrict__ Wt1,  // [32,64]
                        const float* __restrict__ Wr2)  // [16,32]
{
    int t = threadIdx.x;
    int o = t & 31, sl = t >> 5;
    float wt1[64];
    #pragma unroll
    for (int j = 0; j < 64; j++) wt1[j] = Wt1[o * 64 + j];
    float bias = b1[o];
    int oo = o & 15, jb = (o < 16) ? 0 : 16;

    __shared__ float sW2[16 * 33];
    __shared__ float sh1[32][64];
    __shared__ float sh2[32][32];
    for (int i = t; i < 16 * 32; i += 256) sW2[(i >> 5) * 33 + (i & 31)] = Wr2[i];
    __syncthreads();

    for (int nbase = blockIdx.x * 32; nbase < N_NODES; nbase += gridDim.x * 32) {
        for (int i = t; i < 512; i += 256) {
            int n2 = i >> 4, r = i & 15;
            int nn = nbase + n2;
            if (nn < N_NODES)
                *(float4*)&sh1[n2][r * 4] = *(const float4*)&g_h1[nn * 64 + r * 4];
        }
        __syncthreads();
        float hq[4];
        #pragma unroll
        for (int q = 0; q < 4; q++) {
            int nl = sl + 8 * q, node = nbase + nl;
            float h = bias;
            if (node < N_NODES) h += g_agg1[node * 32 + o];
            #pragma unroll
            for (int c = 0; c < 16; c++) {
                float4 hv = *(const float4*)&sh1[nl][c * 4];
                h += wt1[4*c+0]*hv.x + wt1[4*c+1]*hv.y + wt1[4*c+2]*hv.z + wt1[4*c+3]*hv.w;
            }
            hq[q] = tanhf(h);
        }
        #pragma unroll
        for (int q = 0; q < 4; q++) {
            int nl = sl + 8 * q, node = nbase + nl;
            if (node < N_NODES) g_h2[node * 32 + o] = hq[q];
            sh2[nl][o] = hq[q];
        }
        __syncwarp();
        #pragma unroll
        for (int q = 0; q < 4; q++) {
            int nl = sl + 8 * q, node = nbase + nl;
            float p = 0.f;
            #pragma unroll
            for (int c = 0; c < 4; c++) {
                float4 hv = *(const float4*)&sh2[nl][jb + c * 4];
                const float* wrow = &sW2[oo * 33 + jb + c * 4];
                p += wrow[0]*hv.x + wrow[1]*hv.y + wrow[2]*hv.z + wrow[3]*hv.w;
            }
            float other = __shfl_down_sync(0xffffffffu, p, 16);
            if (node < N_NODES && o < 16) g_y2[node * 16 + o] = p + other;
        }
        __syncthreads();
    }
}

// ---------------- node kernel 2 + pooling (unchanged) -----------------------
__global__ void k_node2_pool(const int* __restrict__ batch_raw,
                             const float* __restrict__ b2,   // [16]
                             const float* __restrict__ Wt2)  // [16,32]
{
    int t = threadIdx.x;
    int o = t & 15, sl = t >> 4;
    float wt2[32];
    #pragma unroll
    for (int j = 0; j < 32; j++) wt2[j] = Wt2[o * 32 + j];
    float bias = b2[o];
    int b_is64 = g_b_is64;

    __shared__ float sh2[64][32];

    for (int nbase = blockIdx.x * 64; nbase < N_NODES; nbase += gridDim.x * 64) {
        for (int i = t; i < 512; i += 256) {
            int n2 = i >> 3, r = i & 7;
            int nn = nbase + n2;
            if (nn < N_NODES)
                *(float4*)&sh2[n2][r * 4] = *(const float4*)&g_h2[nn * 32 + r * 4];
        }
        __syncthreads();
        #pragma unroll
        for (int q = 0; q < 4; q++) {
            int nl = sl + 16 * q, node = nbase + nl;
            if (node < N_NODES) {
                float acc = bias + g_agg2[node * 16 + o];
                #pragma unroll
                for (int c = 0; c < 8; c++) {
                    float4 hv = *(const float4*)&sh2[nl][c * 4];
                    acc += wt2[4*c+0]*hv.x + wt2[4*c+1]*hv.y + wt2[4*c+2]*hv.z + wt2[4*c+3]*hv.w;
                }
                int g = b_is64 ? batch_raw[2 * node] : batch_raw[node];
                atomicAdd(&g_pool[g * 16 + o], acc);
                if (o == 0) atomicAdd(&g_cnt[g], 1.0f);
            }
        }
        __syncthreads();
    }
}

// ---------------- final: out = tanh(pool / max(cnt,1)) ----------------------
__global__ void k_final(float* __restrict__ out) {
    int t = blockIdx.x * blockDim.x + threadIdx.x;
    if (t < N_GRAPHS * 16) {
        int g = t >> 4;
        out[t] = tanhf(g_pool[t] / fmaxf(g_cnt[g], 1.0f));
    }
}

extern "C" void kernel_launch(void* const* d_in, const int* in_sizes, int n_in,
                              void* d_out, int out_size) {
    const float* x         = (const float*)d_in[0];
    const int*   ei_raw    = (const int*)d_in[1];
    const int*   batch_raw = (const int*)d_in[2];
    const float* Wr0 = (const float*)d_in[3];
    const float* b0  = (const float*)d_in[4];
    const float* Wt0 = (const float*)d_in[5];
    const float* Wr1 = (const float*)d_in[6];
    const float* b1  = (const float*)d_in[7];
    const float* Wt1 = (const float*)d_in[8];
    const float* Wr2 = (const float*)d_in[9];
    const float* b2  = (const float*)d_in[10];
    const float* Wt2 = (const float*)d_in[11];
    float* out = (float*)d_out;

    k_detect<<<1, 1>>>(ei_raw, batch_raw);
    k_prep<<<2048, 256>>>(x, ei_raw);
    // CSR build (dst-sorted edge list)
    k_hist<<<2048, 256>>>();
    k_scan1<<<391, 256>>>();
    k_scan2<<<1, 512>>>();
    k_scan3<<<391, 256>>>();
    k_place<<<2048, 256>>>();
    // layer 0
    k_agg0<<<(N_NODES * 10 + 255) / 256, 256>>>();
    k_node0A<<<391, 256>>>(Wr0, b0, Wt0);
    k_y1<<<391, 256>>>(Wr1);
    // layer 1
    k_agg1<<<(N_NODES * 8 + 255) / 256, 256>>>();
    k_node1<<<296, 256>>>(b1, Wt1, Wr2);
    // layer 2
    k_agg2<<<(N_NODES * 4 + 255) / 256, 256>>>();
    k_node2_pool<<<296, 256>>>(batch_raw, b2, Wt2);
    k_final<<<16, 256>>>(out);
}